// round 14
// baseline (speedup 1.0000x reference)
#include <cuda_runtime.h>
#include <cuda_fp16.h>
#include <math.h>

#define T_TOTAL 32768
#define NEXP    64
#define HDIM    1024
#define GRID    296            // 2 CTAs/SM, one wave
#define NTHR    256
#define KC      64
#define NCHUNK  (HDIM / KC)    // 16
#define EPS_TIE 1.5e-3f

#define A_LEV   16384          // 128 rows x 128B (fp16, single level)
#define A_BYTES (2 * A_LEV)    // double buffered: 32KB
#define B_CHUNK 8192           // 4 s x 4 npair x 32 lanes x 16B
#define B_BYTES (2 * B_CHUNK)  // 16KB double buffer
#define SMEM_REQ (A_BYTES + B_BYTES)   // 48KB

// W as fp16, stored in mma B-fragment register order
__device__ unsigned char g_Wfrag[NCHUNK * B_CHUNK];

// one thread per 16B fragment group: g = ((chunk*4+s)*4+npair)*32+lane
__global__ void prep_w_kernel(const float* __restrict__ W) {
    int g = blockIdx.x * blockDim.x + threadIdx.x;
    if (g >= NCHUNK * 512) return;
    int lane = g & 31;
    int t = g >> 5;
    int npair = t & 3;  t >>= 2;
    int s = t & 3;
    int chunk = t >> 2;
    int k0 = chunk * KC + s * 16 + (lane & 3) * 2;
    unsigned w[4];
#pragma unroll
    for (int q = 0; q < 2; q++) {
        int e = (npair * 2 + q) * 8 + (lane >> 2);
        const float* We = W + (size_t)e * HDIM;
        w[q * 2 + 0] = (unsigned)__half_as_ushort(__float2half_rn(We[k0]))
                     | ((unsigned)__half_as_ushort(__float2half_rn(We[k0 + 1])) << 16);
        w[q * 2 + 1] = (unsigned)__half_as_ushort(__float2half_rn(We[k0 + 8]))
                     | ((unsigned)__half_as_ushort(__float2half_rn(We[k0 + 9])) << 16);
    }
    *(uint4*)&g_Wfrag[(size_t)g * 16] = make_uint4(w[0], w[1], w[2], w[3]);
}

#define CP_ASYNC16(dst_u32, src) \
    asm volatile("cp.async.cg.shared.global [%0], [%1], 16;" :: "r"(dst_u32), "l"(src))
#define CP_COMMIT()  asm volatile("cp.async.commit_group;")
#define CP_WAIT0()   asm volatile("cp.async.wait_group 0;")

#define LDMATRIX_X4(a, addr)                                            \
    asm volatile("ldmatrix.sync.aligned.m8n8.x4.shared.b16 {%0,%1,%2,%3}, [%4];" \
        : "=r"((a)[0]), "=r"((a)[1]), "=r"((a)[2]), "=r"((a)[3]) : "r"(addr))

#define MMA_F16(d, a, b0, b1)                                           \
    asm volatile("mma.sync.aligned.m16n8k16.row.col.f32.f16.f16.f32 "   \
        "{%0,%1,%2,%3}, {%4,%5,%6,%7}, {%8,%9}, {%0,%1,%2,%3};"         \
        : "+f"((d)[0]), "+f"((d)[1]), "+f"((d)[2]), "+f"((d)[3])        \
        : "r"((a)[0]), "r"((a)[1]), "r"((a)[2]), "r"((a)[3]), "r"(b0), "r"(b1))

__global__ __launch_bounds__(NTHR, 2)
void moe_gate_mma(const float* __restrict__ x,
                  const float* __restrict__ W,
                  float* __restrict__ out,
                  int out_size)
{
    extern __shared__ unsigned char dsm[];
    const unsigned smemA = (unsigned)__cvta_generic_to_shared(dsm);
    const unsigned smemB = smemA + A_BYTES;

    __shared__ int s_nflag;
    __shared__ int s_rows[128];

    const int tid  = threadIdx.x;
    const int w    = tid >> 5;
    const int lane = tid & 31;
    const int wm   = w & 3;           // 4 m-tiles of 32 rows
    const int wn   = w >> 2;          // 2 n-halves of 32 experts
    const int m_base = wm * 32;
    const int n_base = wn * 32;
    const int np0  = wn * 2;

    const int start = (int)(((long long)blockIdx.x * T_TOTAL) / GRID);
    const int count = (int)(((long long)(blockIdx.x + 1) * T_TOTAL) / GRID) - start;
    const float* xblk = x + (size_t)start * HDIM;

    if (tid == 0) s_nflag = 0;

    float acc[2][4][4];
#pragma unroll
    for (int mt = 0; mt < 2; mt++)
#pragma unroll
        for (int nt = 0; nt < 4; nt++)
#pragma unroll
            for (int i = 0; i < 4; i++) acc[mt][nt][i] = 0.0f;

    float4 xr[8];

    auto ldg_x = [&](int c) {
#pragma unroll
        for (int i = 0; i < 8; i++) {
            int idx = i * NTHR + tid;          // 2048 = 128 rows x 16 float4
            int row = idx >> 4, c4 = idx & 15;
            int gr = (row < count) ? row : 0;
            xr[i] = *(const float4*)&xblk[(size_t)gr * HDIM + c * KC + c4 * 4];
        }
    };

    // convert xr -> fp16, store into A buffer `buf` (swizzled)
    auto sts_a = [&](int buf) {
        unsigned char* base = dsm + buf * A_LEV;
#pragma unroll
        for (int i = 0; i < 8; i++) {
            int idx = i * NTHR + tid;
            int row = idx >> 4, c4 = idx & 15;
            unsigned off = (unsigned)(row * 128)
                         + (((unsigned)((c4 >> 1) ^ (row & 7)) << 4) | ((c4 & 1) << 3));
            float4 v = xr[i];
            __half2 h01 = __floats2half2_rn(v.x, v.y);   // v.x in low half
            __half2 h23 = __floats2half2_rn(v.z, v.w);
            *(uint2*)(base + off) = make_uint2(
                *(unsigned*)&h01, *(unsigned*)&h23);
        }
    };

    auto cp_b = [&](int c) {
        unsigned dbase = smemB + (c & 1) * B_CHUNK;
        const unsigned char* src = g_Wfrag + (size_t)c * B_CHUNK;
#pragma unroll
        for (int i = 0; i < 2; i++) {
            int idx = i * NTHR + tid;          // 512 x 16B
            CP_ASYNC16(dbase + idx * 16, src + (size_t)idx * 16);
        }
    };

    // prologue: A(0) staged, x(1) in regs, B(0) resident before barrier
    ldg_x(0);
    cp_b(0); CP_COMMIT();
    sts_a(0);
    ldg_x(1);
    CP_WAIT0();
    __syncthreads();

    for (int c = 0; c < NCHUNK; c++) {
        if (c + 1 < NCHUNK) { cp_b(c + 1); CP_COMMIT(); }

        const unsigned abase = smemA + (c & 1) * A_LEV;
        const unsigned bbase = smemB + (c & 1) * B_CHUNK;

#pragma unroll
        for (int s = 0; s < 4; s++) {
            unsigned a[2][4];
#pragma unroll
            for (int mt = 0; mt < 2; mt++) {
                int arow = m_base + mt * 16 + ((lane >> 3) & 1) * 8 + (lane & 7);
                unsigned addr = abase + arow * 128
                    + ((unsigned)(((s << 1) | ((lane >> 4) & 1)) ^ (arow & 7)) << 4);
                LDMATRIX_X4(a[mt], addr);
            }
            unsigned boff = bbase + ((s * 4 + np0) * 512) + lane * 16;
            uint4 b0, b1;
            asm volatile("ld.shared.v4.u32 {%0,%1,%2,%3}, [%4];"
                : "=r"(b0.x), "=r"(b0.y), "=r"(b0.z), "=r"(b0.w) : "r"(boff));
            asm volatile("ld.shared.v4.u32 {%0,%1,%2,%3}, [%4];"
                : "=r"(b1.x), "=r"(b1.y), "=r"(b1.z), "=r"(b1.w) : "r"(boff + 512));
#pragma unroll
            for (int mt = 0; mt < 2; mt++) {
                MMA_F16(acc[mt][0], a[mt], b0.x, b0.y);
                MMA_F16(acc[mt][1], a[mt], b0.z, b0.w);
                MMA_F16(acc[mt][2], a[mt], b1.x, b1.y);
                MMA_F16(acc[mt][3], a[mt], b1.z, b1.w);
            }
        }

        if (c + 1 < NCHUNK) sts_a((c + 1) & 1);   // buffer last read in chunk c-1
        if (c + 2 < NCHUNK) ldg_x(c + 2);
        if (c + 1 < NCHUNK) CP_WAIT0();           // everyone's B(c+1) retired pre-barrier
        __syncthreads();
    }

    // ---------------- epilogue ----------------
    float* L = (float*)dsm;   // pitch 68 floats, conflict-free
    {
        int r0l = lane >> 2, c0l = (lane & 3) * 2;
#pragma unroll
        for (int mt = 0; mt < 2; mt++)
#pragma unroll
            for (int nt = 0; nt < 4; nt++) {
                int row = m_base + mt * 16 + r0l;
                int col = n_base + nt * 8 + c0l;
                *(float2*)&L[row * 68 + col]       = make_float2(acc[mt][nt][0], acc[mt][nt][1]);
                *(float2*)&L[(row + 8) * 68 + col] = make_float2(acc[mt][nt][2], acc[mt][nt][3]);
            }
    }
    __syncthreads();

    // --- phase 1: flag near-tie rows (top-3 gap test) ---
    if (tid < 128 && tid < count) {
        int row = tid;
        float v1 = -INFINITY, v2 = -INFINITY, v3 = -INFINITY;
#pragma unroll
        for (int e = 0; e < NEXP; e++) {
            float lv = L[row * 68 + e];
            if (lv > v1)      { v3 = v2; v2 = v1; v1 = lv; }
            else if (lv > v2) { v3 = v2; v2 = lv; }
            else if (lv > v3) { v3 = lv; }
        }
        if (v1 - v2 < EPS_TIE || v2 - v3 < EPS_TIE) {
            int slot = atomicAdd(&s_nflag, 1);
            s_rows[slot] = row;
        }
    }
    __syncthreads();

    // --- phase 2: cooperative exact-fp32 recompute of flagged rows ---
    {
        const int nf = s_nflag;
        const int e  = tid >> 2;        // expert 0..63
        const int q  = tid & 3;         // k-quarter
        for (int f = 0; f < nf; f++) {
            int row = s_rows[f];
            const float* xq = xblk + (size_t)row * HDIM + q * 256;
            const float* Wq = W + (size_t)e * HDIM + q * 256;
            float d0 = 0.f, d1 = 0.f, d2 = 0.f, d3 = 0.f;
#pragma unroll 8
            for (int kk = 0; kk < 64; kk++) {
                float4 xa = *(const float4*)&xq[kk * 4];
                float4 wa = *(const float4*)&Wq[kk * 4];
                d0 = fmaf(xa.x, wa.x, d0);
                d1 = fmaf(xa.y, wa.y, d1);
                d2 = fmaf(xa.z, wa.z, d2);
                d3 = fmaf(xa.w, wa.w, d3);
            }
            float v = (d0 + d1) + (d2 + d3);
            v += __shfl_xor_sync(0xffffffffu, v, 1);
            v += __shfl_xor_sync(0xffffffffu, v, 2);
            if (q == 0) L[row * 68 + e] = v;
        }
        if (nf) __syncthreads();
    }

    // --- phase 3: softmax + top-2 from (possibly corrected) logits ---
    if (tid < 128 && tid < count) {
        int row = tid;
        float l[64];
#pragma unroll
        for (int i = 0; i < 16; i++)
            *(float4*)&l[i * 4] = *(const float4*)&L[row * 68 + i * 4];

        float mx = l[0];
#pragma unroll
        for (int e = 1; e < NEXP; e++) mx = fmaxf(mx, l[e]);
        float sum = 0.0f;
#pragma unroll
        for (int e = 0; e < NEXP; e++) sum += expf(l[e] - mx);

        float v1 = -INFINITY, v2 = -INFINITY;
        int   i1 = 0, i2 = 0;
#pragma unroll
        for (int e = 0; e < NEXP; e++) {
            float lv = l[e];
            if (lv > v1)      { v2 = v1; i2 = i1; v1 = lv; i1 = e; }
            else if (lv > v2) { v2 = lv; i2 = e; }
        }

        float p1 = expf(v1 - mx) / sum;
        float p2 = expf(v2 - mx) / sum;
        float e21 = expf(p2 - p1);
        float s1  = 1.0f / (1.0f + e21);
        float s2  = e21 * s1;

        int t = start + row;
        *(float2*)&out[2 * (size_t)t] = make_float2(s1, s2);
        *(float2*)&out[2 * (size_t)T_TOTAL + 2 * (size_t)t] =
            make_float2((float)i1, (float)i2);
    }

    // tail (scalar zero output + anything past 4*T)
    if (blockIdx.x == 0 && tid < 32) {
        for (int p = 4 * T_TOTAL + tid; p < out_size; p += 32)
            out[p] = 0.0f;
    }
}

extern "C" void kernel_launch(void* const* d_in, const int* in_sizes, int n_in,
                              void* d_out, int out_size)
{
    const float* x = (const float*)d_in[0];
    const float* W = (const float*)d_in[1];
    float* out = (float*)d_out;

    static bool attr_set = false;
    if (!attr_set) {
        cudaFuncSetAttribute(moe_gate_mma,
                             cudaFuncAttributeMaxDynamicSharedMemorySize, SMEM_REQ);
        attr_set = true;
    }

    prep_w_kernel<<<(NCHUNK * 512 + 255) / 256, 256>>>(W);
    moe_gate_mma<<<GRID, NTHR, SMEM_REQ>>>(x, W, out, out_size);
}

// round 15
// speedup vs baseline: 3.3704x; 3.3704x over previous
#include <cuda_runtime.h>
#include <cuda_fp16.h>
#include <math.h>

#define T_TOTAL 32768
#define NEXP    64
#define HDIM    1024
#define GRID    296            // 2 CTAs/SM, one wave
#define NTHR    256
#define KC      64
#define NCHUNK  (HDIM / KC)    // 16
#define EPS_TIE 8e-4f

#define A_LEV   16384          // 128 rows x 128B (fp16, single level)
#define A_BYTES (2 * A_LEV)    // double buffered: 32KB
#define B_CHUNK 8192           // 4 s x 4 npair x 32 lanes x 16B
#define B_BYTES (2 * B_CHUNK)  // 16KB double buffer
#define SMEM_REQ (A_BYTES + B_BYTES)   // 48KB

// W as fp16, stored in mma B-fragment register order
__device__ unsigned char g_Wfrag[NCHUNK * B_CHUNK];

// one thread per 16B fragment group: g = ((chunk*4+s)*4+npair)*32+lane
__global__ void prep_w_kernel(const float* __restrict__ W) {
    int g = blockIdx.x * blockDim.x + threadIdx.x;
    if (g >= NCHUNK * 512) return;
    int lane = g & 31;
    int t = g >> 5;
    int npair = t & 3;  t >>= 2;
    int s = t & 3;
    int chunk = t >> 2;
    int k0 = chunk * KC + s * 16 + (lane & 3) * 2;
    unsigned w[4];
#pragma unroll
    for (int q = 0; q < 2; q++) {
        int e = (npair * 2 + q) * 8 + (lane >> 2);
        const float* We = W + (size_t)e * HDIM;
        w[q * 2 + 0] = (unsigned)__half_as_ushort(__float2half_rn(We[k0]))
                     | ((unsigned)__half_as_ushort(__float2half_rn(We[k0 + 1])) << 16);
        w[q * 2 + 1] = (unsigned)__half_as_ushort(__float2half_rn(We[k0 + 8]))
                     | ((unsigned)__half_as_ushort(__float2half_rn(We[k0 + 9])) << 16);
    }
    *(uint4*)&g_Wfrag[(size_t)g * 16] = make_uint4(w[0], w[1], w[2], w[3]);
}

#define CP_ASYNC16(dst_u32, src) \
    asm volatile("cp.async.cg.shared.global [%0], [%1], 16;" :: "r"(dst_u32), "l"(src))
#define CP_COMMIT()  asm volatile("cp.async.commit_group;")
#define CP_WAIT0()   asm volatile("cp.async.wait_group 0;")

#define LDMATRIX_X4(a, addr)                                            \
    asm volatile("ldmatrix.sync.aligned.m8n8.x4.shared.b16 {%0,%1,%2,%3}, [%4];" \
        : "=r"((a)[0]), "=r"((a)[1]), "=r"((a)[2]), "=r"((a)[3]) : "r"(addr))

#define MMA_F16(d, a, b0, b1)                                           \
    asm volatile("mma.sync.aligned.m16n8k16.row.col.f32.f16.f16.f32 "   \
        "{%0,%1,%2,%3}, {%4,%5,%6,%7}, {%8,%9}, {%0,%1,%2,%3};"         \
        : "+f"((d)[0]), "+f"((d)[1]), "+f"((d)[2]), "+f"((d)[3])        \
        : "r"((a)[0]), "r"((a)[1]), "r"((a)[2]), "r"((a)[3]), "r"(b0), "r"(b1))

__global__ __launch_bounds__(NTHR, 2)
void moe_gate_mma(const float* __restrict__ x,
                  const float* __restrict__ W,
                  float* __restrict__ out,
                  int out_size)
{
    extern __shared__ unsigned char dsm[];
    const unsigned smemA = (unsigned)__cvta_generic_to_shared(dsm);
    const unsigned smemB = smemA + A_BYTES;

    __shared__ int s_nflag;
    __shared__ int s_rows[128];

    const int tid  = threadIdx.x;
    const int w    = tid >> 5;
    const int lane = tid & 31;
    const int wm   = w & 3;           // 4 m-tiles of 32 rows
    const int wn   = w >> 2;          // 2 n-halves of 32 experts
    const int m_base = wm * 32;
    const int n_base = wn * 32;
    const int np0  = wn * 2;

    const int start = (int)(((long long)blockIdx.x * T_TOTAL) / GRID);
    const int count = (int)(((long long)(blockIdx.x + 1) * T_TOTAL) / GRID) - start;
    const float* xblk = x + (size_t)start * HDIM;

    if (tid == 0) s_nflag = 0;

    float acc[2][4][4];
#pragma unroll
    for (int mt = 0; mt < 2; mt++)
#pragma unroll
        for (int nt = 0; nt < 4; nt++)
#pragma unroll
            for (int i = 0; i < 4; i++) acc[mt][nt][i] = 0.0f;

    float4 xr[8];

    auto ldg_x = [&](int c) {
#pragma unroll
        for (int i = 0; i < 8; i++) {
            int idx = i * NTHR + tid;          // 2048 = 128 rows x 16 float4
            int row = idx >> 4, c4 = idx & 15;
            int gr = (row < count) ? row : 0;
            xr[i] = *(const float4*)&xblk[(size_t)gr * HDIM + c * KC + c4 * 4];
        }
    };

    // convert xr -> fp16, store into A buffer `buf` (swizzled)
    auto sts_a = [&](int buf) {
        unsigned char* base = dsm + buf * A_LEV;
#pragma unroll
        for (int i = 0; i < 8; i++) {
            int idx = i * NTHR + tid;
            int row = idx >> 4, c4 = idx & 15;
            unsigned off = (unsigned)(row * 128)
                         + (((unsigned)((c4 >> 1) ^ (row & 7)) << 4) | ((c4 & 1) << 3));
            float4 v = xr[i];
            __half2 h01 = __floats2half2_rn(v.x, v.y);   // v.x in low half
            __half2 h23 = __floats2half2_rn(v.z, v.w);
            *(uint2*)(base + off) = make_uint2(
                *(unsigned*)&h01, *(unsigned*)&h23);
        }
    };

    auto cp_b = [&](int c) {
        unsigned dbase = smemB + (c & 1) * B_CHUNK;
        const unsigned char* src = g_Wfrag + (size_t)c * B_CHUNK;
#pragma unroll
        for (int i = 0; i < 2; i++) {
            int idx = i * NTHR + tid;          // 512 x 16B
            CP_ASYNC16(dbase + idx * 16, src + (size_t)idx * 16);
        }
    };

    // prologue: A(0) staged, x(1) in regs, B(0) resident before barrier
    ldg_x(0);
    cp_b(0); CP_COMMIT();
    sts_a(0);
    ldg_x(1);
    CP_WAIT0();
    __syncthreads();

    for (int c = 0; c < NCHUNK; c++) {
        if (c + 1 < NCHUNK) { cp_b(c + 1); CP_COMMIT(); }

        const unsigned abase = smemA + (c & 1) * A_LEV;
        const unsigned bbase = smemB + (c & 1) * B_CHUNK;

#pragma unroll
        for (int s = 0; s < 4; s++) {
            unsigned a[2][4];
#pragma unroll
            for (int mt = 0; mt < 2; mt++) {
                int arow = m_base + mt * 16 + ((lane >> 3) & 1) * 8 + (lane & 7);
                unsigned addr = abase + arow * 128
                    + ((unsigned)(((s << 1) | ((lane >> 4) & 1)) ^ (arow & 7)) << 4);
                LDMATRIX_X4(a[mt], addr);
            }
            unsigned boff = bbase + ((s * 4 + np0) * 512) + lane * 16;
            uint4 b0, b1;
            asm volatile("ld.shared.v4.u32 {%0,%1,%2,%3}, [%4];"
                : "=r"(b0.x), "=r"(b0.y), "=r"(b0.z), "=r"(b0.w) : "r"(boff));
            asm volatile("ld.shared.v4.u32 {%0,%1,%2,%3}, [%4];"
                : "=r"(b1.x), "=r"(b1.y), "=r"(b1.z), "=r"(b1.w) : "r"(boff + 512));
#pragma unroll
            for (int mt = 0; mt < 2; mt++) {
                MMA_F16(acc[mt][0], a[mt], b0.x, b0.y);
                MMA_F16(acc[mt][1], a[mt], b0.z, b0.w);
                MMA_F16(acc[mt][2], a[mt], b1.x, b1.y);
                MMA_F16(acc[mt][3], a[mt], b1.z, b1.w);
            }
        }

        if (c + 1 < NCHUNK) sts_a((c + 1) & 1);   // buffer last read in chunk c-1
        if (c + 2 < NCHUNK) ldg_x(c + 2);
        if (c + 1 < NCHUNK) CP_WAIT0();           // everyone's B(c+1) retired pre-barrier
        __syncthreads();
    }

    // ---------------- epilogue ----------------
    float* L = (float*)dsm;   // pitch 68 floats, conflict-free
    {
        int r0l = lane >> 2, c0l = (lane & 3) * 2;
#pragma unroll
        for (int mt = 0; mt < 2; mt++)
#pragma unroll
            for (int nt = 0; nt < 4; nt++) {
                int row = m_base + mt * 16 + r0l;
                int col = n_base + nt * 8 + c0l;
                *(float2*)&L[row * 68 + col]       = make_float2(acc[mt][nt][0], acc[mt][nt][1]);
                *(float2*)&L[(row + 8) * 68 + col] = make_float2(acc[mt][nt][2], acc[mt][nt][3]);
            }
    }
    __syncthreads();

    // --- phase 1: flag near-tie rows (top-3 gap test) ---
    if (tid < 128 && tid < count) {
        int row = tid;
        float v1 = -INFINITY, v2 = -INFINITY, v3 = -INFINITY;
#pragma unroll
        for (int e = 0; e < NEXP; e++) {
            float lv = L[row * 68 + e];
            if (lv > v1)      { v3 = v2; v2 = v1; v1 = lv; }
            else if (lv > v2) { v3 = v2; v2 = lv; }
            else if (lv > v3) { v3 = lv; }
        }
        if (v1 - v2 < EPS_TIE || v2 - v3 < EPS_TIE) {
            int slot = atomicAdd(&s_nflag, 1);
            s_rows[slot] = row;
        }
    }
    __syncthreads();

    // --- phase 2: cooperative exact-fp32 recompute of flagged rows ---
    // Coalesced: warp w owns experts 8w..8w+7; 32 lanes split k contiguously,
    // so every warp LDG.128 touches 4 consecutive 128B lines (minimal wavefronts).
    {
        const int nf = s_nflag;
        for (int f = 0; f < nf; f++) {
            int row = s_rows[f];
            const float* xrow = xblk + (size_t)row * HDIM;
#pragma unroll
            for (int ei = 0; ei < 8; ei++) {
                int e = w * 8 + ei;
                const float* We = W + (size_t)e * HDIM;
                float d0 = 0.f, d1 = 0.f, d2 = 0.f, d3 = 0.f;
#pragma unroll
                for (int kk = 0; kk < 8; kk++) {
                    int off = (kk * 32 + lane) * 4;
                    float4 xa = *(const float4*)&xrow[off];
                    float4 wa = *(const float4*)&We[off];
                    d0 = fmaf(xa.x, wa.x, d0);
                    d1 = fmaf(xa.y, wa.y, d1);
                    d2 = fmaf(xa.z, wa.z, d2);
                    d3 = fmaf(xa.w, wa.w, d3);
                }
                float v = (d0 + d1) + (d2 + d3);
                v += __shfl_xor_sync(0xffffffffu, v, 16);
                v += __shfl_xor_sync(0xffffffffu, v, 8);
                v += __shfl_xor_sync(0xffffffffu, v, 4);
                v += __shfl_xor_sync(0xffffffffu, v, 2);
                v += __shfl_xor_sync(0xffffffffu, v, 1);
                if (lane == 0) L[row * 68 + e] = v;
            }
        }
        if (nf) __syncthreads();
    }

    // --- phase 3: softmax + top-2 from (possibly corrected) logits ---
    if (tid < 128 && tid < count) {
        int row = tid;
        float l[64];
#pragma unroll
        for (int i = 0; i < 16; i++)
            *(float4*)&l[i * 4] = *(const float4*)&L[row * 68 + i * 4];

        float mx = l[0];
#pragma unroll
        for (int e = 1; e < NEXP; e++) mx = fmaxf(mx, l[e]);
        float sum = 0.0f;
#pragma unroll
        for (int e = 0; e < NEXP; e++) sum += expf(l[e] - mx);

        float v1 = -INFINITY, v2 = -INFINITY;
        int   i1 = 0, i2 = 0;
#pragma unroll
        for (int e = 0; e < NEXP; e++) {
            float lv = l[e];
            if (lv > v1)      { v2 = v1; i2 = i1; v1 = lv; i1 = e; }
            else if (lv > v2) { v2 = lv; i2 = e; }
        }

        float p1 = expf(v1 - mx) / sum;
        float p2 = expf(v2 - mx) / sum;
        float e21 = expf(p2 - p1);
        float s1  = 1.0f / (1.0f + e21);
        float s2  = e21 * s1;

        int t = start + row;
        *(float2*)&out[2 * (size_t)t] = make_float2(s1, s2);
        *(float2*)&out[2 * (size_t)T_TOTAL + 2 * (size_t)t] =
            make_float2((float)i1, (float)i2);
    }

    // tail (scalar zero output + anything past 4*T)
    if (blockIdx.x == 0 && tid < 32) {
        for (int p = 4 * T_TOTAL + tid; p < out_size; p += 32)
            out[p] = 0.0f;
    }
}

extern "C" void kernel_launch(void* const* d_in, const int* in_sizes, int n_in,
                              void* d_out, int out_size)
{
    const float* x = (const float*)d_in[0];
    const float* W = (const float*)d_in[1];
    float* out = (float*)d_out;

    static bool attr_set = false;
    if (!attr_set) {
        cudaFuncSetAttribute(moe_gate_mma,
                             cudaFuncAttributeMaxDynamicSharedMemorySize, SMEM_REQ);
        attr_set = true;
    }

    prep_w_kernel<<<(NCHUNK * 512 + 255) / 256, 256>>>(W);
    moe_gate_mma<<<GRID, NTHR, SMEM_REQ>>>(x, W, out, out_size);
}